// round 5
// baseline (speedup 1.0000x reference)
#include <cuda_runtime.h>
#include <cuda_bf16.h>
#include <cstdint>
#include <cstddef>

#define NPOS 8192
#define NNEG 4096
#define DIM 64
#define MROWS 24576          // NPOS + 4*NNEG
#define XROWS 12288
#define SIMCOLS 24576
#define LRUC 1

#define BM 128
#define BN 128

typedef unsigned long long ull;
typedef uint32_t u32;

// ---------------- device scratch (no allocs allowed) ----------------
__device__ __align__(256) __nv_bfloat16 g_Abf[NPOS * 128];    // [row][Ah(64) | Al(64)]
__device__ __align__(256) __nv_bfloat16 g_Bbf[MROWS * 128];   // [row][Bh(64) | Bl(64)]
__device__ float g_get[NPOS * DIM];
__device__ float g_counts[NPOS];
__device__ float g_vis[NPOS];
__device__ ull   g_amax[NPOS];

// ---------------- PTX helpers ----------------
__device__ __forceinline__ u32 smem_u32(const void* p) {
    u32 a; asm("{ .reg .u64 t; cvta.to.shared.u64 t, %1; cvt.u32.u64 %0, t; }" : "=r"(a) : "l"(p));
    return a;
}
__device__ __forceinline__ void cpasync16(u32 dst, const void* src) {
    asm volatile("cp.async.cg.shared.global [%0], [%1], 16;" :: "r"(dst), "l"(src) : "memory");
}
#define CP_COMMIT()  asm volatile("cp.async.commit_group;" ::: "memory")
#define CP_WAIT(n)   asm volatile("cp.async.wait_group %0;" :: "n"(n) : "memory")

__device__ __forceinline__ void ldsm4(u32& r0, u32& r1, u32& r2, u32& r3, u32 addr) {
    asm volatile("ldmatrix.sync.aligned.m8n8.x4.shared.b16 {%0,%1,%2,%3}, [%4];"
                 : "=r"(r0), "=r"(r1), "=r"(r2), "=r"(r3) : "r"(addr));
}
__device__ __forceinline__ void mma16816(float& d0, float& d1, float& d2, float& d3,
                                         u32 a0, u32 a1, u32 a2, u32 a3, u32 b0, u32 b1) {
    asm volatile("mma.sync.aligned.m16n8k16.row.col.f32.bf16.bf16.f32 "
                 "{%0,%1,%2,%3}, {%4,%5,%6,%7}, {%8,%9}, {%0,%1,%2,%3};"
                 : "+f"(d0), "+f"(d1), "+f"(d2), "+f"(d3)
                 : "r"(a0), "r"(a1), "r"(a2), "r"(a3), "r"(b0), "r"(b1));
}
__device__ __forceinline__ void stg_cs_f2(float* p, float a, float b) {
    asm volatile("st.global.cs.v2.f32 [%0], {%1,%2};" :: "l"(p), "f"(a), "f"(b) : "memory");
}
__device__ __forceinline__ u32 fkey(float v) {
    u32 u = __float_as_uint(v);
    return (u & 0x80000000u) ? ~u : (u | 0x80000000u);
}

// ---------------- split + zero scratch (fused) ----------------
__global__ void split_kernel(const float* __restrict__ x, const float* __restrict__ mem) {
    const int nA = NPOS * DIM, nTot = nA + MROWS * DIM;
    const int gs = gridDim.x * blockDim.x;
    const int t0 = blockIdx.x * blockDim.x + threadIdx.x;
    for (int i = t0; i < nTot; i += gs) {
        float v; __nv_bfloat16* base; int k;
        if (i < nA) { v = x[i];        base = g_Abf + (size_t)(i >> 6) * 128;        k = i & 63; }
        else { int j = i - nA; v = mem[j]; base = g_Bbf + (size_t)(j >> 6) * 128;    k = j & 63; }
        __nv_bfloat16 h = __float2bfloat16_rn(v);
        float r = v - __bfloat162float(h);
        base[k]      = h;
        base[64 + k] = __float2bfloat16_rn(r);
    }
    for (int j = t0; j < NPOS * DIM; j += gs) g_get[j] = 0.0f;
    for (int j = t0; j < NPOS; j += gs) { g_counts[j] = 0.0f; g_vis[j] = 0.0f; g_amax[j] = 0ull; }
}

__global__ void vis_kernel(const int* __restrict__ visible) {
    int i = blockIdx.x * blockDim.x + threadIdx.x;
    if (i < NPOS / 2) g_vis[visible[i]] = 1.0f;
}

// ---------------- bf16 split-GEMM via mma.sync + fused argmax partials ----------------
// C[8192,24576] = A*B^T with A=Ah+Al, B=Bh+Bl; sim = AhBh + AlBh + AhBl.
// CTA tile 128x128, warp tile 64x32 (2x4 warps), 2 CTAs/SM.
// ks-outer loop with fragment reuse: 12 ldmatrix.x4 per ks instead of 18.
__global__ void __launch_bounds__(256, 2)
gemm_mma(const int* __restrict__ y, float* __restrict__ C) {
    extern __shared__ char smem[];
    const u32 sb = smem_u32(smem);
    const u32 As = sb;             // 128 rows * 256B = 32KB
    const u32 Bs = sb + 32768;     // 128 rows * 256B = 32KB
    int* ys = (int*)(smem + 65536);

    const int tid  = threadIdx.x;
    const int lane = tid & 31;
    const int w    = tid >> 5;
    const int wm   = w >> 2, wn = w & 3;
    const int m0   = blockIdx.y * BM;
    const int n0   = blockIdx.x * BN;
    const bool domax = (n0 < NPOS);

    // ---- cp.async loads (hi + lo halves) ----
#pragma unroll
    for (int h = 0; h < 2; h++) {
#pragma unroll
        for (int i = 0; i < 4; i++) {           // A: 1024 chunks of 16B
            int idx = tid + i * 256;
            int r = idx >> 3, c = idx & 7;
            u32 dst = As + r * 256 + (u32)(((h * 8) | ((c ^ r) & 7)) * 16);
            cpasync16(dst, g_Abf + (size_t)(m0 + r) * 128 + h * 64 + c * 8);
        }
#pragma unroll
        for (int i = 0; i < 4; i++) {           // B: 1024 chunks of 16B
            int idx = tid + i * 256;
            int r = idx >> 3, c = idx & 7;
            u32 dst = Bs + r * 256 + (u32)(((h * 8) | ((c ^ r) & 7)) * 16);
            cpasync16(dst, g_Bbf + (size_t)(n0 + r) * 128 + h * 64 + c * 8);
        }
    }
    CP_COMMIT();
    if (domax && tid < BM) ys[tid] = y[m0 + tid];

    float acc[4][4][4];
#pragma unroll
    for (int mi = 0; mi < 4; mi++)
#pragma unroll
        for (int ni = 0; ni < 4; ni++)
#pragma unroll
            for (int q = 0; q < 4; q++) acc[mi][ni][q] = 0.0f;

    CP_WAIT(0);
    __syncthreads();

    const int wr = wm * 64, wc = wn * 32;

#pragma unroll
    for (int ks = 0; ks < 4; ks++) {
        // --- Ah fragments (ch 0..7) ---
        u32 ah[4][4];
#pragma unroll
        for (int mi = 0; mi < 4; mi++) {
            int row = wr + mi * 16 + (lane & 15);
            int ch  = 2 * ks + (lane >> 4);
            u32 ad  = As + row * 256 + (u32)(((ch & 8) | ((ch ^ row) & 7)) * 16);
            ldsm4(ah[mi][0], ah[mi][1], ah[mi][2], ah[mi][3], ad);
        }
        // --- Bh fragments ---
        u32 bh[2][4];
#pragma unroll
        for (int j = 0; j < 2; j++) {
            int n  = wc + j * 16 + (lane & 7) + ((lane >> 4) << 3);
            int ch = 2 * ks + ((lane >> 3) & 1);
            u32 bd = Bs + n * 256 + (u32)(((ch & 8) | ((ch ^ n) & 7)) * 16);
            ldsm4(bh[j][0], bh[j][1], bh[j][2], bh[j][3], bd);
        }
        // pass 0: Ah * Bh
#pragma unroll
        for (int mi = 0; mi < 4; mi++)
#pragma unroll
            for (int ni = 0; ni < 4; ni++) {
                int j = ni >> 1, o = (ni & 1) * 2;
                mma16816(acc[mi][ni][0], acc[mi][ni][1], acc[mi][ni][2], acc[mi][ni][3],
                         ah[mi][0], ah[mi][1], ah[mi][2], ah[mi][3], bh[j][o], bh[j][o + 1]);
            }
        // --- Al fragments (ch 8..15) ---
        u32 al[4][4];
#pragma unroll
        for (int mi = 0; mi < 4; mi++) {
            int row = wr + mi * 16 + (lane & 15);
            int ch  = 8 + 2 * ks + (lane >> 4);
            u32 ad  = As + row * 256 + (u32)(((ch & 8) | ((ch ^ row) & 7)) * 16);
            ldsm4(al[mi][0], al[mi][1], al[mi][2], al[mi][3], ad);
        }
        // pass 1: Al * Bh
#pragma unroll
        for (int mi = 0; mi < 4; mi++)
#pragma unroll
            for (int ni = 0; ni < 4; ni++) {
                int j = ni >> 1, o = (ni & 1) * 2;
                mma16816(acc[mi][ni][0], acc[mi][ni][1], acc[mi][ni][2], acc[mi][ni][3],
                         al[mi][0], al[mi][1], al[mi][2], al[mi][3], bh[j][o], bh[j][o + 1]);
            }
        // --- Bl fragments ---
        u32 bl[2][4];
#pragma unroll
        for (int j = 0; j < 2; j++) {
            int n  = wc + j * 16 + (lane & 7) + ((lane >> 4) << 3);
            int ch = 8 + 2 * ks + ((lane >> 3) & 1);
            u32 bd = Bs + n * 256 + (u32)(((ch & 8) | ((ch ^ n) & 7)) * 16);
            ldsm4(bl[j][0], bl[j][1], bl[j][2], bl[j][3], bd);
        }
        // pass 2: Ah * Bl
#pragma unroll
        for (int mi = 0; mi < 4; mi++)
#pragma unroll
            for (int ni = 0; ni < 4; ni++) {
                int j = ni >> 1, o = (ni & 1) * 2;
                mma16816(acc[mi][ni][0], acc[mi][ni][1], acc[mi][ni][2], acc[mi][ni][3],
                         ah[mi][0], ah[mi][1], ah[mi][2], ah[mi][3], bl[j][o], bl[j][o + 1]);
            }
    }

    // ---- epilogue: streaming stores + fused per-row argmax partials ----
#pragma unroll
    for (int mi = 0; mi < 4; mi++) {
        int lr = wr + mi * 16 + (lane >> 2);
        float* p0 = C + (size_t)(m0 + lr) * SIMCOLS + n0 + wc + (lane & 3) * 2;
        float* p1 = p0 + (size_t)8 * SIMCOLS;
        ull k0 = 0, k1 = 0;
        int yv0 = -1, yv1 = -1;
        if (domax) { yv0 = ys[lr]; yv1 = ys[lr + 8]; }
#pragma unroll
        for (int ni = 0; ni < 4; ni++) {
            float c0 = acc[mi][ni][0], c1 = acc[mi][ni][1];
            float c2 = acc[mi][ni][2], c3 = acc[mi][ni][3];
            stg_cs_f2(p0 + ni * 8, c0, c1);
            stg_cs_f2(p1 + ni * 8, c2, c3);
            if (domax) {
                int col = n0 + wc + ni * 8 + (lane & 3) * 2;
                float v0 = c0 + (col     == yv0 ? 2.0f : 0.0f);
                float v1 = c1 + (col + 1 == yv0 ? 2.0f : 0.0f);
                float v2 = c2 + (col     == yv1 ? 2.0f : 0.0f);
                float v3 = c3 + (col + 1 == yv1 ? 2.0f : 0.0f);
                ull q;
                q = ((ull)fkey(v0) << 32) | (u32)(0xFFFFFFFFu - (u32)col);       if (q > k0) k0 = q;
                q = ((ull)fkey(v1) << 32) | (u32)(0xFFFFFFFFu - (u32)(col + 1)); if (q > k0) k0 = q;
                q = ((ull)fkey(v2) << 32) | (u32)(0xFFFFFFFFu - (u32)col);       if (q > k1) k1 = q;
                q = ((ull)fkey(v3) << 32) | (u32)(0xFFFFFFFFu - (u32)(col + 1)); if (q > k1) k1 = q;
            }
        }
        if (domax) {
#pragma unroll
            for (int o2 = 1; o2 <= 2; o2 <<= 1) {
                ull t0 = __shfl_xor_sync(0xffffffffu, k0, o2); if (t0 > k0) k0 = t0;
                ull t1 = __shfl_xor_sync(0xffffffffu, k1, o2); if (t1 > k1) k1 = t1;
            }
            if ((lane & 3) == 0) {
                atomicMax(&g_amax[m0 + lr], k0);
                atomicMax(&g_amax[m0 + lr + 8], k1);
            }
        }
    }
}

// ---------------- finalize argmax + segment sums (fused) ----------------
__global__ void segsum_kernel(const float* __restrict__ x, float* __restrict__ out_y) {
    int i = blockIdx.x;          // source row
    int t = threadIdx.x;         // 0..63
    ull k = g_amax[i];
    int idx = (int)(0xFFFFFFFFu - (u32)(k & 0xFFFFFFFFull));
    if (t == 0) { out_y[i] = (float)idx; atomicAdd(&g_counts[idx], 1.0f); }
    atomicAdd(&g_get[idx * DIM + t], x[(size_t)i * DIM + t]);
}

// ---------------- memory update + normalize + slot writes ----------------
__global__ void update_kernel(const float* __restrict__ x, const float* __restrict__ memory,
                              const float* __restrict__ params, float* __restrict__ outm) {
    int r = blockIdx.x;
    int t = threadIdx.x;
    if (r < NPOS) {
        float mom   = params[3];
        float cnt   = g_counts[r];
        float valid = (cnt > 0.1f ? 1.0f : 0.0f) * g_vis[r];
        float msc   = valid * mom + 1.0f - valid;
        float gsc   = (1.0f - mom) * valid;
        float denom = cnt + 1e-8f;
        float v0 = memory[(size_t)r * DIM + t]      * msc + (g_get[r * DIM + t]      / denom) * gsc;
        float v1 = memory[(size_t)r * DIM + t + 32] * msc + (g_get[r * DIM + t + 32] / denom) * gsc;
        float ss = v0 * v0 + v1 * v1;
#pragma unroll
        for (int o = 16; o; o >>= 1) ss += __shfl_xor_sync(0xffffffffu, ss, o);
        float inv = 1.0f / fmaxf(sqrtf(ss), 1e-12f);
        outm[(size_t)r * DIM + t]      = v0 * inv;
        outm[(size_t)r * DIM + t + 32] = v1 * inv;
    } else if (r >= NPOS + LRUC * NNEG && r < NPOS + LRUC * NNEG + NNEG) {
        int xs = NPOS + (r - (NPOS + LRUC * NNEG));
        outm[(size_t)r * DIM + t]      = x[(size_t)xs * DIM + t];
        outm[(size_t)r * DIM + t + 32] = x[(size_t)xs * DIM + t + 32];
    } else {
        outm[(size_t)r * DIM + t]      = memory[(size_t)r * DIM + t];
        outm[(size_t)r * DIM + t + 32] = memory[(size_t)r * DIM + t + 32];
    }
}

// ---------------- launch ----------------
extern "C" void kernel_launch(void* const* d_in, const int* in_sizes, int n_in,
                              void* d_out, int out_size) {
    const float* x = nullptr;
    const int*   y = nullptr;
    const int*   visible = nullptr;
    const float* memory = nullptr;
    const float* params = nullptr;
    for (int i = 0; i < n_in; i++) {
        switch (in_sizes[i]) {
            case XROWS * DIM: x = (const float*)d_in[i]; break;
            case NPOS:        y = (const int*)d_in[i]; break;
            case NPOS / 2:    visible = (const int*)d_in[i]; break;
            case MROWS * DIM: memory = (const float*)d_in[i]; break;
            case 4:           params = (const float*)d_in[i]; break;
            default: break;
        }
    }

    float* sim     = (float*)d_out;
    float* out_y   = sim + (size_t)NPOS * SIMCOLS;
    float* out_mem = out_y + NPOS;

    const int SMEM_TOTAL = 65536 + 512;   // A(32K) + B(32K) + y tile
    cudaFuncSetAttribute(gemm_mma, cudaFuncAttributeMaxDynamicSharedMemorySize, SMEM_TOTAL);

    split_kernel<<<2048, 256>>>(x, memory);
    vis_kernel<<<(NPOS / 2 + 255) / 256, 256>>>(visible);
    gemm_mma<<<dim3(SIMCOLS / BN, NPOS / BM), 256, SMEM_TOTAL>>>(y, sim);
    segsum_kernel<<<NPOS, 64>>>(x, out_y);
    update_kernel<<<MROWS, 32>>>(x, memory, params, out_mem);
}

// round 6
// speedup vs baseline: 1.4558x; 1.4558x over previous
#include <cuda_runtime.h>
#include <cuda_bf16.h>
#include <cstdint>
#include <cstddef>

#define NPOS 8192
#define NNEG 4096
#define DIM 64
#define MROWS 24576          // NPOS + 4*NNEG
#define XROWS 12288
#define SIMCOLS 24576
#define LRUC 1

#define BM 128
#define BN 128

typedef unsigned long long ull;
typedef uint32_t u32;

// ---------------- device scratch (no allocs allowed) ----------------
__device__ __align__(256) __nv_bfloat16 g_Abf[NPOS * 128];    // [row][Ah(64) | Al(64)]
__device__ __align__(256) __nv_bfloat16 g_Bbf[MROWS * 128];   // [row][Bh(64) | Bl(64)]
__device__ float g_get[NPOS * DIM];
__device__ float g_counts[NPOS];
__device__ float g_vis[NPOS];
__device__ ull   g_amax[NPOS];

// ---------------- PTX helpers ----------------
__device__ __forceinline__ u32 smem_u32(const void* p) {
    u32 a; asm("{ .reg .u64 t; cvta.to.shared.u64 t, %1; cvt.u32.u64 %0, t; }" : "=r"(a) : "l"(p));
    return a;
}
__device__ __forceinline__ void cpasync16(u32 dst, const void* src) {
    asm volatile("cp.async.cg.shared.global [%0], [%1], 16;" :: "r"(dst), "l"(src) : "memory");
}
#define CP_COMMIT()  asm volatile("cp.async.commit_group;" ::: "memory")
#define CP_WAIT(n)   asm volatile("cp.async.wait_group %0;" :: "n"(n) : "memory")

__device__ __forceinline__ void ldsm4(u32& r0, u32& r1, u32& r2, u32& r3, u32 addr) {
    asm volatile("ldmatrix.sync.aligned.m8n8.x4.shared.b16 {%0,%1,%2,%3}, [%4];"
                 : "=r"(r0), "=r"(r1), "=r"(r2), "=r"(r3) : "r"(addr));
}
__device__ __forceinline__ void mma16816(float& d0, float& d1, float& d2, float& d3,
                                         u32 a0, u32 a1, u32 a2, u32 a3, u32 b0, u32 b1) {
    asm volatile("mma.sync.aligned.m16n8k16.row.col.f32.bf16.bf16.f32 "
                 "{%0,%1,%2,%3}, {%4,%5,%6,%7}, {%8,%9}, {%0,%1,%2,%3};"
                 : "+f"(d0), "+f"(d1), "+f"(d2), "+f"(d3)
                 : "r"(a0), "r"(a1), "r"(a2), "r"(a3), "r"(b0), "r"(b1));
}
__device__ __forceinline__ u32 fkey(float v) {
    u32 u = __float_as_uint(v);
    return (u & 0x80000000u) ? ~u : (u | 0x80000000u);
}

// ---------------- split + zero scratch (fused) ----------------
__global__ void split_kernel(const float* __restrict__ x, const float* __restrict__ mem) {
    const int nA = NPOS * DIM, nTot = nA + MROWS * DIM;
    const int gs = gridDim.x * blockDim.x;
    const int t0 = blockIdx.x * blockDim.x + threadIdx.x;
    for (int i = t0; i < nTot; i += gs) {
        float v; __nv_bfloat16* base; int k;
        if (i < nA) { v = x[i];        base = g_Abf + (size_t)(i >> 6) * 128;        k = i & 63; }
        else { int j = i - nA; v = mem[j]; base = g_Bbf + (size_t)(j >> 6) * 128;    k = j & 63; }
        __nv_bfloat16 h = __float2bfloat16_rn(v);
        float r = v - __bfloat162float(h);
        base[k]      = h;
        base[64 + k] = __float2bfloat16_rn(r);
    }
    for (int j = t0; j < NPOS * DIM; j += gs) g_get[j] = 0.0f;
    for (int j = t0; j < NPOS; j += gs) { g_counts[j] = 0.0f; g_vis[j] = 0.0f; g_amax[j] = 0ull; }
}

__global__ void vis_kernel(const int* __restrict__ visible) {
    int i = blockIdx.x * blockDim.x + threadIdx.x;
    if (i < NPOS / 2) g_vis[visible[i]] = 1.0f;
}

// ---------------- bf16 split-GEMM via mma.sync + fused argmax partials ----------------
// C[8192,24576] = A*B^T with A=Ah+Al, B=Bh+Bl; sim = AhBh + AhBl + AlBh.
// CTA tile 128x128, warp tile 64x32 (2x4 warps), 2 CTAs/SM.
// ks-outer, pass order (Ah,Bh),(Ah,Bl),(Al,Bh): only `af` held across passes;
// b-fragments share one buffer. 14 ldmatrix.x4 per ks (vs 18), bounded regs.
__global__ void __launch_bounds__(256, 2)
gemm_mma(const int* __restrict__ y, float* __restrict__ C) {
    extern __shared__ char smem[];
    const u32 sb = smem_u32(smem);
    const u32 As = sb;             // 128 rows * 256B = 32KB
    const u32 Bs = sb + 32768;     // 128 rows * 256B = 32KB
    int* ys = (int*)(smem + 65536);

    const int tid  = threadIdx.x;
    const int lane = tid & 31;
    const int w    = tid >> 5;
    const int wm   = w >> 2, wn = w & 3;
    const int m0   = blockIdx.y * BM;
    const int n0   = blockIdx.x * BN;
    const bool domax = (n0 < NPOS);

    // ---- cp.async loads (hi + lo halves) ----
#pragma unroll
    for (int h = 0; h < 2; h++) {
#pragma unroll
        for (int i = 0; i < 4; i++) {           // A: 1024 chunks of 16B
            int idx = tid + i * 256;
            int r = idx >> 3, c = idx & 7;
            u32 dst = As + r * 256 + (u32)(((h * 8) | ((c ^ r) & 7)) * 16);
            cpasync16(dst, g_Abf + (size_t)(m0 + r) * 128 + h * 64 + c * 8);
        }
#pragma unroll
        for (int i = 0; i < 4; i++) {           // B: 1024 chunks of 16B
            int idx = tid + i * 256;
            int r = idx >> 3, c = idx & 7;
            u32 dst = Bs + r * 256 + (u32)(((h * 8) | ((c ^ r) & 7)) * 16);
            cpasync16(dst, g_Bbf + (size_t)(n0 + r) * 128 + h * 64 + c * 8);
        }
    }
    CP_COMMIT();
    if (domax && tid < BM) ys[tid] = y[m0 + tid];

    float acc[4][4][4];
#pragma unroll
    for (int mi = 0; mi < 4; mi++)
#pragma unroll
        for (int ni = 0; ni < 4; ni++)
#pragma unroll
            for (int q = 0; q < 4; q++) acc[mi][ni][q] = 0.0f;

    CP_WAIT(0);
    __syncthreads();

    const int wr = wm * 64, wc = wn * 32;

    // smem address helpers
    auto a_addr = [&](int mi, int ch) -> u32 {
        int row = wr + mi * 16 + (lane & 15);
        int c   = ch + (lane >> 4);
        return As + row * 256 + (u32)(((c & 8) | ((c ^ row) & 7)) * 16);
    };
    auto b_addr = [&](int j, int ch) -> u32 {
        int n = wc + j * 16 + (lane & 7) + ((lane >> 4) << 3);
        int c = ch + ((lane >> 3) & 1);
        return Bs + n * 256 + (u32)(((c & 8) | ((c ^ n) & 7)) * 16);
    };

#pragma unroll
    for (int ks = 0; ks < 4; ks++) {
        u32 af[4][4];
        u32 bf[2][4];
        // --- Ah (held across pass0 and pass1) ---
#pragma unroll
        for (int mi = 0; mi < 4; mi++)
            ldsm4(af[mi][0], af[mi][1], af[mi][2], af[mi][3], a_addr(mi, 2 * ks));
        // --- Bh ---
#pragma unroll
        for (int j = 0; j < 2; j++)
            ldsm4(bf[j][0], bf[j][1], bf[j][2], bf[j][3], b_addr(j, 2 * ks));
        // pass 0: Ah * Bh
#pragma unroll
        for (int mi = 0; mi < 4; mi++)
#pragma unroll
            for (int ni = 0; ni < 4; ni++) {
                int j = ni >> 1, o = (ni & 1) * 2;
                mma16816(acc[mi][ni][0], acc[mi][ni][1], acc[mi][ni][2], acc[mi][ni][3],
                         af[mi][0], af[mi][1], af[mi][2], af[mi][3], bf[j][o], bf[j][o + 1]);
            }
        // --- Bl (overwrites bf) ---
#pragma unroll
        for (int j = 0; j < 2; j++)
            ldsm4(bf[j][0], bf[j][1], bf[j][2], bf[j][3], b_addr(j, 8 + 2 * ks));
        // pass 1: Ah * Bl
#pragma unroll
        for (int mi = 0; mi < 4; mi++)
#pragma unroll
            for (int ni = 0; ni < 4; ni++) {
                int j = ni >> 1, o = (ni & 1) * 2;
                mma16816(acc[mi][ni][0], acc[mi][ni][1], acc[mi][ni][2], acc[mi][ni][3],
                         af[mi][0], af[mi][1], af[mi][2], af[mi][3], bf[j][o], bf[j][o + 1]);
            }
        // --- Al (overwrites af) + Bh reload (overwrites bf) ---
#pragma unroll
        for (int mi = 0; mi < 4; mi++)
            ldsm4(af[mi][0], af[mi][1], af[mi][2], af[mi][3], a_addr(mi, 8 + 2 * ks));
#pragma unroll
        for (int j = 0; j < 2; j++)
            ldsm4(bf[j][0], bf[j][1], bf[j][2], bf[j][3], b_addr(j, 2 * ks));
        // pass 2: Al * Bh
#pragma unroll
        for (int mi = 0; mi < 4; mi++)
#pragma unroll
            for (int ni = 0; ni < 4; ni++) {
                int j = ni >> 1, o = (ni & 1) * 2;
                mma16816(acc[mi][ni][0], acc[mi][ni][1], acc[mi][ni][2], acc[mi][ni][3],
                         af[mi][0], af[mi][1], af[mi][2], af[mi][3], bf[j][o], bf[j][o + 1]);
            }
    }

    // ---- epilogue: stores + fused per-row argmax partials ----
#pragma unroll
    for (int mi = 0; mi < 4; mi++) {
        int lr = wr + mi * 16 + (lane >> 2);
        float* p0 = C + (size_t)(m0 + lr) * SIMCOLS + n0 + wc + (lane & 3) * 2;
        float* p1 = p0 + (size_t)8 * SIMCOLS;
        ull k0 = 0, k1 = 0;
        int yv0 = -1, yv1 = -1;
        if (domax) { yv0 = ys[lr]; yv1 = ys[lr + 8]; }
#pragma unroll
        for (int ni = 0; ni < 4; ni++) {
            float c0 = acc[mi][ni][0], c1 = acc[mi][ni][1];
            float c2 = acc[mi][ni][2], c3 = acc[mi][ni][3];
            *(float2*)(p0 + ni * 8) = make_float2(c0, c1);
            *(float2*)(p1 + ni * 8) = make_float2(c2, c3);
            if (domax) {
                int col = n0 + wc + ni * 8 + (lane & 3) * 2;
                float v0 = c0 + (col     == yv0 ? 2.0f : 0.0f);
                float v1 = c1 + (col + 1 == yv0 ? 2.0f : 0.0f);
                float v2 = c2 + (col     == yv1 ? 2.0f : 0.0f);
                float v3 = c3 + (col + 1 == yv1 ? 2.0f : 0.0f);
                ull q;
                q = ((ull)fkey(v0) << 32) | (u32)(0xFFFFFFFFu - (u32)col);       if (q > k0) k0 = q;
                q = ((ull)fkey(v1) << 32) | (u32)(0xFFFFFFFFu - (u32)(col + 1)); if (q > k0) k0 = q;
                q = ((ull)fkey(v2) << 32) | (u32)(0xFFFFFFFFu - (u32)col);       if (q > k1) k1 = q;
                q = ((ull)fkey(v3) << 32) | (u32)(0xFFFFFFFFu - (u32)(col + 1)); if (q > k1) k1 = q;
            }
        }
        if (domax) {
#pragma unroll
            for (int o2 = 1; o2 <= 2; o2 <<= 1) {
                ull t0 = __shfl_xor_sync(0xffffffffu, k0, o2); if (t0 > k0) k0 = t0;
                ull t1 = __shfl_xor_sync(0xffffffffu, k1, o2); if (t1 > k1) k1 = t1;
            }
            if ((lane & 3) == 0) {
                atomicMax(&g_amax[m0 + lr], k0);
                atomicMax(&g_amax[m0 + lr + 8], k1);
            }
        }
    }
}

// ---------------- finalize argmax + segment sums (fused) ----------------
__global__ void segsum_kernel(const float* __restrict__ x, float* __restrict__ out_y) {
    int i = blockIdx.x;          // source row
    int t = threadIdx.x;         // 0..63
    ull k = g_amax[i];
    int idx = (int)(0xFFFFFFFFu - (u32)(k & 0xFFFFFFFFull));
    if (t == 0) { out_y[i] = (float)idx; atomicAdd(&g_counts[idx], 1.0f); }
    atomicAdd(&g_get[idx * DIM + t], x[(size_t)i * DIM + t]);
}

// ---------------- memory update + normalize + slot writes ----------------
__global__ void update_kernel(const float* __restrict__ x, const float* __restrict__ memory,
                              const float* __restrict__ params, float* __restrict__ outm) {
    int r = blockIdx.x;
    int t = threadIdx.x;
    if (r < NPOS) {
        float mom   = params[3];
        float cnt   = g_counts[r];
        float valid = (cnt > 0.1f ? 1.0f : 0.0f) * g_vis[r];
        float msc   = valid * mom + 1.0f - valid;
        float gsc   = (1.0f - mom) * valid;
        float denom = cnt + 1e-8f;
        float v0 = memory[(size_t)r * DIM + t]      * msc + (g_get[r * DIM + t]      / denom) * gsc;
        float v1 = memory[(size_t)r * DIM + t + 32] * msc + (g_get[r * DIM + t + 32] / denom) * gsc;
        float ss = v0 * v0 + v1 * v1;
#pragma unroll
        for (int o = 16; o; o >>= 1) ss += __shfl_xor_sync(0xffffffffu, ss, o);
        float inv = 1.0f / fmaxf(sqrtf(ss), 1e-12f);
        outm[(size_t)r * DIM + t]      = v0 * inv;
        outm[(size_t)r * DIM + t + 32] = v1 * inv;
    } else if (r >= NPOS + LRUC * NNEG && r < NPOS + LRUC * NNEG + NNEG) {
        int xs = NPOS + (r - (NPOS + LRUC * NNEG));
        outm[(size_t)r * DIM + t]      = x[(size_t)xs * DIM + t];
        outm[(size_t)r * DIM + t + 32] = x[(size_t)xs * DIM + t + 32];
    } else {
        outm[(size_t)r * DIM + t]      = memory[(size_t)r * DIM + t];
        outm[(size_t)r * DIM + t + 32] = memory[(size_t)r * DIM + t + 32];
    }
}

// ---------------- launch ----------------
extern "C" void kernel_launch(void* const* d_in, const int* in_sizes, int n_in,
                              void* d_out, int out_size) {
    const float* x = nullptr;
    const int*   y = nullptr;
    const int*   visible = nullptr;
    const float* memory = nullptr;
    const float* params = nullptr;
    for (int i = 0; i < n_in; i++) {
        switch (in_sizes[i]) {
            case XROWS * DIM: x = (const float*)d_in[i]; break;
            case NPOS:        y = (const int*)d_in[i]; break;
            case NPOS / 2:    visible = (const int*)d_in[i]; break;
            case MROWS * DIM: memory = (const float*)d_in[i]; break;
            case 4:           params = (const float*)d_in[i]; break;
            default: break;
        }
    }

    float* sim     = (float*)d_out;
    float* out_y   = sim + (size_t)NPOS * SIMCOLS;
    float* out_mem = out_y + NPOS;

    const int SMEM_TOTAL = 65536 + 512;   // A(32K) + B(32K) + y tile
    cudaFuncSetAttribute(gemm_mma, cudaFuncAttributeMaxDynamicSharedMemorySize, SMEM_TOTAL);

    split_kernel<<<2048, 256>>>(x, memory);
    vis_kernel<<<(NPOS / 2 + 255) / 256, 256>>>(visible);
    gemm_mma<<<dim3(SIMCOLS / BN, NPOS / BM), 256, SMEM_TOTAL>>>(y, sim);
    segsum_kernel<<<NPOS, 64>>>(x, out_y);
    update_kernel<<<MROWS, 32>>>(x, memory, params, out_mem);
}